// round 1
// baseline (speedup 1.0000x reference)
#include <cuda_runtime.h>

#define BB 32
#define RR 512
#define TT 128
#define HH 64

// ---- scratch (device globals; no allocations) ----
__device__ float g_k [BB*RR*HH];
__device__ float g_v [BB*RR*HH];
__device__ float g_rp[BB*RR*HH];
__device__ float g_q [BB*TT*HH];
__device__ float g_tp[BB*TT*HH];

// =====================================================================
// Kernel 1: robot encoder (7->64 relu ->64 relu) fused with K,V,rp proj
// warp-per-row; 8 warps/block
// =====================================================================
__global__ void k_robot(const float* __restrict__ x,
    const float* __restrict__ w1, const float* __restrict__ b1,
    const float* __restrict__ w2, const float* __restrict__ b2,
    const float* __restrict__ wk, const float* __restrict__ bk,
    const float* __restrict__ wv, const float* __restrict__ bv,
    const float* __restrict__ aw1)
{
    __shared__ float sA[8][64];
    __shared__ float sB[8][64];
    int wid = threadIdx.x >> 5, lane = threadIdx.x & 31;
    int row = blockIdx.x * 8 + wid;
    const float* xr = x + row * 7;
    float xv[7];
#pragma unroll
    for (int i = 0; i < 7; i++) xv[i] = xr[i];
    int c0 = lane, c1 = lane + 32;

    float ha = b1[c0], hb = b1[c1];
#pragma unroll
    for (int i = 0; i < 7; i++) { ha += xv[i]*w1[i*64+c0]; hb += xv[i]*w1[i*64+c1]; }
    sA[wid][c0] = fmaxf(ha, 0.f); sA[wid][c1] = fmaxf(hb, 0.f);
    __syncwarp();

    float ga = b2[c0], gb = b2[c1];
#pragma unroll 8
    for (int j = 0; j < 64; j++) { float s = sA[wid][j]; ga += s*w2[j*64+c0]; gb += s*w2[j*64+c1]; }
    sB[wid][c0] = fmaxf(ga, 0.f); sB[wid][c1] = fmaxf(gb, 0.f);
    __syncwarp();

    float ka = bk[c0], kb = bk[c1];
    float va = bv[c0], vb = bv[c1];
    float pa = 0.f,    pb = 0.f;
#pragma unroll 8
    for (int j = 0; j < 64; j++) {
        float s = sB[wid][j];
        ka += s*wk[j*64+c0];        kb += s*wk[j*64+c1];
        va += s*wv[j*64+c0];        vb += s*wv[j*64+c1];
        pa += s*aw1[(64+j)*64+c0];  pb += s*aw1[(64+j)*64+c1];
    }
    g_k [row*64+c0] = ka; g_k [row*64+c1] = kb;
    g_v [row*64+c0] = va; g_v [row*64+c1] = vb;
    g_rp[row*64+c0] = pa; g_rp[row*64+c1] = pb;
}

// =====================================================================
// Kernel 2: task encoder (6->64 relu ->64 relu) fused with Q projection
// =====================================================================
__global__ void k_task(const float* __restrict__ x,
    const float* __restrict__ w1, const float* __restrict__ b1,
    const float* __restrict__ w2, const float* __restrict__ b2,
    const float* __restrict__ wq, const float* __restrict__ bq)
{
    __shared__ float sA[8][64];
    __shared__ float sB[8][64];
    int wid = threadIdx.x >> 5, lane = threadIdx.x & 31;
    int row = blockIdx.x * 8 + wid;
    const float* xr = x + row * 6;
    float xv[6];
#pragma unroll
    for (int i = 0; i < 6; i++) xv[i] = xr[i];
    int c0 = lane, c1 = lane + 32;

    float ha = b1[c0], hb = b1[c1];
#pragma unroll
    for (int i = 0; i < 6; i++) { ha += xv[i]*w1[i*64+c0]; hb += xv[i]*w1[i*64+c1]; }
    sA[wid][c0] = fmaxf(ha, 0.f); sA[wid][c1] = fmaxf(hb, 0.f);
    __syncwarp();

    float ga = b2[c0], gb = b2[c1];
#pragma unroll 8
    for (int j = 0; j < 64; j++) { float s = sA[wid][j]; ga += s*w2[j*64+c0]; gb += s*w2[j*64+c1]; }
    sB[wid][c0] = fmaxf(ga, 0.f); sB[wid][c1] = fmaxf(gb, 0.f);
    __syncwarp();

    float qa = bq[c0], qb = bq[c1];
#pragma unroll 8
    for (int j = 0; j < 64; j++) { float s = sB[wid][j]; qa += s*wq[j*64+c0]; qb += s*wq[j*64+c1]; }
    g_q[row*64+c0] = qa; g_q[row*64+c1] = qb;
}

// =====================================================================
// Kernel 3: attention (tasks attend robots), 4 heads HD=16
// block per (b,t); 256 threads.  Produces g_tp = (ctx@wo+bo)@a_w1[:H]+a_b1
// =====================================================================
__global__ void k_attn(const float* __restrict__ wo, const float* __restrict__ bo,
                       const float* __restrict__ aw1, const float* __restrict__ ab1)
{
    int bt = blockIdx.x;
    int b  = bt >> 7;           // T=128
    __shared__ float qs[64];
    __shared__ float lg[4][512];
    __shared__ float red[8];
    __shared__ float invs[4];
    __shared__ float ctxp[4][68];
    __shared__ float ctxs[64];
    __shared__ float tfs[64];
    int t = threadIdx.x, lane = t & 31, wid = t >> 5;

    if (t < 64) qs[t] = g_q[bt*64 + t];
    __syncthreads();

    // logits[h][r] = q_h . k_{r,h} / 4
    const float* kb = g_k + (size_t)b*RR*64;
#pragma unroll
    for (int it = 0; it < 8; it++) {
        int idx = t + it*256;
        int h = idx >> 9, r = idx & 511;
        const float* kr = kb + r*64 + h*16;
        const float* qh = qs + h*16;
        float d = 0.f;
#pragma unroll
        for (int i = 0; i < 16; i += 4) {
            float4 kv = *(const float4*)(kr + i);
            d += qh[i]*kv.x + qh[i+1]*kv.y + qh[i+2]*kv.z + qh[i+3]*kv.w;
        }
        lg[h][r] = d * 0.25f;
    }
    __syncthreads();

    // per-head softmax over 512
    for (int h = 0; h < 4; h++) {
        float v0 = lg[h][t], v1 = lg[h][t+256];
        float m = fmaxf(v0, v1);
#pragma unroll
        for (int o = 16; o; o >>= 1) m = fmaxf(m, __shfl_xor_sync(0xffffffffu, m, o));
        if (lane == 0) red[wid] = m;
        __syncthreads();
        m = red[0];
#pragma unroll
        for (int i = 1; i < 8; i++) m = fmaxf(m, red[i]);
        __syncthreads();
        float e0 = __expf(v0 - m), e1 = __expf(v1 - m);
        lg[h][t] = e0; lg[h][t+256] = e1;
        float s = e0 + e1;
#pragma unroll
        for (int o = 16; o; o >>= 1) s += __shfl_xor_sync(0xffffffffu, s, o);
        if (lane == 0) red[wid] = s;
        __syncthreads();
        if (t == 0) {
            float ss = 0.f;
#pragma unroll
            for (int i = 0; i < 8; i++) ss += red[i];
            invs[h] = 1.f / ss;
        }
        __syncthreads();
    }

    // ctx[col] = sum_r attn[h][r] * v[r][col]
    {
        const float* vbp = g_v + (size_t)b*RR*64;
        int part = t >> 6, col = t & 63, h = col >> 4;
        int rbase = part * 128;
        float s = 0.f;
#pragma unroll 4
        for (int r = 0; r < 128; r++)
            s += lg[h][rbase + r] * vbp[(size_t)(rbase + r)*64 + col];
        ctxp[part][col] = s;
    }
    __syncthreads();
    if (t < 64)
        ctxs[t] = (ctxp[0][t] + ctxp[1][t] + ctxp[2][t] + ctxp[3][t]) * invs[t >> 4];
    __syncthreads();
    if (t < 64) {
        float o = bo[t];
#pragma unroll 8
        for (int j = 0; j < 64; j++) o += ctxs[j]*wo[j*64+t];
        tfs[t] = o;
    }
    __syncthreads();
    if (t < 64) {
        float p = ab1[t];                    // fold a_b1 into tp
#pragma unroll 8
        for (int j = 0; j < 64; j++) p += tfs[j]*aw1[j*64+t];
        g_tp[bt*64 + t] = p;
    }
}

// =====================================================================
// Kernel 4 (dominant): pairwise MLP + softmax over robots
// block per (b,t); 128 threads; 8 tiles of 64 robots
// per-thread register tile: 2 robots x 8 h2-cols
// =====================================================================
#define MMA_STEP(av0, av1, row) do {                                          \
    const float4 Wa = *(const float4*)(&W2s[(row)][cb]);                      \
    const float4 Wb = *(const float4*)(&W2s[(row)][cb+4]);                    \
    acc0[0] += (av0)*Wa.x; acc0[1] += (av0)*Wa.y;                             \
    acc0[2] += (av0)*Wa.z; acc0[3] += (av0)*Wa.w;                             \
    acc0[4] += (av0)*Wb.x; acc0[5] += (av0)*Wb.y;                             \
    acc0[6] += (av0)*Wb.z; acc0[7] += (av0)*Wb.w;                             \
    acc1[0] += (av1)*Wa.x; acc1[1] += (av1)*Wa.y;                             \
    acc1[2] += (av1)*Wa.z; acc1[3] += (av1)*Wa.w;                             \
    acc1[4] += (av1)*Wb.x; acc1[5] += (av1)*Wb.y;                             \
    acc1[6] += (av1)*Wb.z; acc1[7] += (av1)*Wb.w;                             \
} while (0)

__global__ void __launch_bounds__(128) k_pair(
    const float* __restrict__ aw2, const float* __restrict__ ab2,
    const float* __restrict__ aw3, float* __restrict__ out)
{
    int bt = blockIdx.x;
    int b  = bt >> 7;
    __shared__ __align__(16) float W2s[64][36];   // a_w2 [64][32], padded row
    __shared__ float b2s[32], w3s[32];
    __shared__ __align__(16) float tps[64];
    __shared__ __align__(16) float h1s[64][68];   // robots x H, padded
    __shared__ float sp[4][72];                   // partial scores [c-group][rr]
    __shared__ float sc[512];
    __shared__ float red[8];
    int t = threadIdx.x, lane = t & 31, wid = t >> 5;

    for (int i = t; i < 2048; i += 128) W2s[i >> 5][i & 31] = aw2[i];
    if (t < 32) { b2s[t] = ab2[t]; w3s[t] = aw3[t]; }
    if (t < 64) tps[t] = g_tp[bt*64 + t];
    __syncthreads();

    int tx = t & 3, tyr = t >> 2;
    int cb = tx * 8, rrb = tyr * 2;
    const float* rpb = g_rp + (size_t)b*RR*64;

    for (int tile = 0; tile < 8; tile++) {
        int r0 = tile * 64;
        // ---- build h1 tile: relu(tp + rp) ----
#pragma unroll
        for (int i = 0; i < 8; i++) {
            int lin = t + i*128;              // 0..1023
            int rr = lin >> 4, j4 = lin & 15;
            float4 rv = *(const float4*)(rpb + (size_t)(r0 + rr)*64 + j4*4);
            float4 tv = *(const float4*)(tps + j4*4);
            float4 hv;
            hv.x = fmaxf(rv.x + tv.x, 0.f);
            hv.y = fmaxf(rv.y + tv.y, 0.f);
            hv.z = fmaxf(rv.z + tv.z, 0.f);
            hv.w = fmaxf(rv.w + tv.w, 0.f);
            *(float4*)(&h1s[rr][j4*4]) = hv;
        }
        __syncthreads();

        // ---- GEMM [64 x 32] = h1[64 x 64] @ W2[64 x 32] ----
        float acc0[8], acc1[8];
#pragma unroll
        for (int c = 0; c < 8; c++) { float bb = b2s[cb + c]; acc0[c] = bb; acc1[c] = bb; }
#pragma unroll
        for (int j4 = 0; j4 < 16; j4++) {
            float4 A0 = *(const float4*)(&h1s[rrb  ][j4*4]);
            float4 A1 = *(const float4*)(&h1s[rrb+1][j4*4]);
            MMA_STEP(A0.x, A1.x, j4*4 + 0);
            MMA_STEP(A0.y, A1.y, j4*4 + 1);
            MMA_STEP(A0.z, A1.z, j4*4 + 2);
            MMA_STEP(A0.w, A1.w, j4*4 + 3);
        }

        // ---- epilogue: relu, dot with a_w3 (a_b3 cancels in softmax) ----
        float p0 = 0.f, p1 = 0.f;
#pragma unroll
        for (int c = 0; c < 8; c++) {
            float w3v = w3s[cb + c];
            p0 += fmaxf(acc0[c], 0.f) * w3v;
            p1 += fmaxf(acc1[c], 0.f) * w3v;
        }
        sp[tx][rrb] = p0; sp[tx][rrb+1] = p1;
        __syncthreads();
        if (t < 64) sc[r0 + t] = sp[0][t] + sp[1][t] + sp[2][t] + sp[3][t];
        __syncthreads();
    }

    // ---- softmax over 512 robots ----
    float v0 = sc[t], v1 = sc[t+128], v2 = sc[t+256], v3 = sc[t+384];
    float m = fmaxf(fmaxf(v0, v1), fmaxf(v2, v3));
#pragma unroll
    for (int o = 16; o; o >>= 1) m = fmaxf(m, __shfl_xor_sync(0xffffffffu, m, o));
    if (lane == 0) red[wid] = m;
    __syncthreads();
    m = fmaxf(fmaxf(red[0], red[1]), fmaxf(red[2], red[3]));
    v0 = __expf(v0 - m); v1 = __expf(v1 - m); v2 = __expf(v2 - m); v3 = __expf(v3 - m);
    float s = v0 + v1 + v2 + v3;
#pragma unroll
    for (int o = 16; o; o >>= 1) s += __shfl_xor_sync(0xffffffffu, s, o);
    if (lane == 0) red[4 + wid] = s;
    __syncthreads();
    s = red[4] + red[5] + red[6] + red[7];
    float inv = 1.f / s;
    float* op = out + (size_t)bt * 512;
    op[t]     = v0 * inv;
    op[t+128] = v1 * inv;
    op[t+256] = v2 * inv;
    op[t+384] = v3 * inv;
}

// =====================================================================
extern "C" void kernel_launch(void* const* d_in, const int* in_sizes, int n_in,
                              void* d_out, int out_size)
{
    (void)in_sizes; (void)n_in; (void)out_size;
    const float* robot = (const float*)d_in[0];
    const float* task  = (const float*)d_in[1];
    const float* r_w1  = (const float*)d_in[2];
    const float* r_b1  = (const float*)d_in[3];
    const float* r_w2  = (const float*)d_in[4];
    const float* r_b2  = (const float*)d_in[5];
    const float* t_w1  = (const float*)d_in[6];
    const float* t_b1  = (const float*)d_in[7];
    const float* t_w2  = (const float*)d_in[8];
    const float* t_b2  = (const float*)d_in[9];
    const float* wq    = (const float*)d_in[10];
    const float* bq    = (const float*)d_in[11];
    const float* wk    = (const float*)d_in[12];
    const float* bk    = (const float*)d_in[13];
    const float* wv    = (const float*)d_in[14];
    const float* bv    = (const float*)d_in[15];
    const float* wo    = (const float*)d_in[16];
    const float* bo    = (const float*)d_in[17];
    const float* a_w1  = (const float*)d_in[18];
    const float* a_b1  = (const float*)d_in[19];
    const float* a_w2  = (const float*)d_in[20];
    const float* a_b2  = (const float*)d_in[21];
    const float* a_w3  = (const float*)d_in[22];

    k_robot<<<BB*RR/8, 256>>>(robot, r_w1, r_b1, r_w2, r_b2, wk, bk, wv, bv, a_w1);
    k_task <<<BB*TT/8, 256>>>(task, t_w1, t_b1, t_w2, t_b2, wq, bq);
    k_attn <<<BB*TT,   256>>>(wo, bo, a_w1, a_b1);
    k_pair <<<BB*TT,   128>>>(a_w2, a_b2, a_w3, (float*)d_out);
}

// round 3
// speedup vs baseline: 1.3509x; 1.3509x over previous
#include <cuda_runtime.h>

#define BB 32
#define RR 512
#define TT 128
#define HH 64

// ---- scratch (device globals; no allocations) ----
__device__ float g_k [BB*RR*HH];
__device__ float g_v [BB*RR*HH];
__device__ float g_rp[BB*RR*HH];
__device__ float g_q [BB*TT*HH];
__device__ float g_tp[BB*TT*HH];

// ---- packed fp32x2 helpers (Blackwell FFMA2 path) ----
__device__ __forceinline__ unsigned long long pack2(float a) {
    unsigned long long r;
    asm("mov.b64 %0, {%1, %1};" : "=l"(r) : "f"(a));
    return r;
}
__device__ __forceinline__ void fma2(unsigned long long& d, unsigned long long a, unsigned long long b) {
    asm("fma.rn.f32x2 %0, %1, %2, %3;" : "=l"(d) : "l"(a), "l"(b), "l"(d));
}
__device__ __forceinline__ float2 unpack2(unsigned long long v) {
    float2 f;
    asm("mov.b64 {%0, %1}, %2;" : "=f"(f.x), "=f"(f.y) : "l"(v));
    return f;
}

// =====================================================================
// Kernel 1: robot encoder (7->64 relu ->64 relu) fused with K,V,rp proj
// 2 rows per warp, float2 column pairs -> 4x fewer LDG instructions
// =====================================================================
__global__ void __launch_bounds__(256) k_robot(const float* __restrict__ x,
    const float* __restrict__ w1, const float* __restrict__ b1,
    const float* __restrict__ w2, const float* __restrict__ b2,
    const float* __restrict__ wk, const float* __restrict__ bk,
    const float* __restrict__ wv, const float* __restrict__ bv,
    const float* __restrict__ aw1)
{
    __shared__ float sA[8][2][64];
    __shared__ float sB[8][2][64];
    int wid = threadIdx.x >> 5, lane = threadIdx.x & 31;
    int r0 = blockIdx.x * 16 + wid * 2;
    const float* x0 = x + r0 * 7;
    const float* x1 = x0 + 7;
    int c = lane * 2;

    float xv0[7], xv1[7];
#pragma unroll
    for (int i = 0; i < 7; i++) { xv0[i] = x0[i]; xv1[i] = x1[i]; }

    // layer 1
    float b1c0 = b1[c], b1c1 = b1[c+1];
    float h00 = b1c0, h01 = b1c1, h10 = b1c0, h11 = b1c1;
#pragma unroll
    for (int i = 0; i < 7; i++) {
        float2 w = *(const float2*)&w1[i*64 + c];
        h00 += xv0[i]*w.x; h01 += xv0[i]*w.y;
        h10 += xv1[i]*w.x; h11 += xv1[i]*w.y;
    }
    sA[wid][0][c] = fmaxf(h00,0.f); sA[wid][0][c+1] = fmaxf(h01,0.f);
    sA[wid][1][c] = fmaxf(h10,0.f); sA[wid][1][c+1] = fmaxf(h11,0.f);
    __syncwarp();

    // layer 2
    float b2c0 = b2[c], b2c1 = b2[c+1];
    float g00 = b2c0, g01 = b2c1, g10 = b2c0, g11 = b2c1;
#pragma unroll 8
    for (int j = 0; j < 64; j++) {
        float2 w = *(const float2*)&w2[j*64 + c];
        float s0 = sA[wid][0][j], s1 = sA[wid][1][j];
        g00 += s0*w.x; g01 += s0*w.y;
        g10 += s1*w.x; g11 += s1*w.y;
    }
    sB[wid][0][c] = fmaxf(g00,0.f); sB[wid][0][c+1] = fmaxf(g01,0.f);
    sB[wid][1][c] = fmaxf(g10,0.f); sB[wid][1][c+1] = fmaxf(g11,0.f);
    __syncwarp();

    // fused K, V, rp projections (12 accumulators)
    float k00 = bk[c], k01 = bk[c+1], k10 = bk[c], k11 = bk[c+1];
    float v00 = bv[c], v01 = bv[c+1], v10 = bv[c], v11 = bv[c+1];
    float p00 = 0.f, p01 = 0.f, p10 = 0.f, p11 = 0.f;
#pragma unroll 4
    for (int j = 0; j < 64; j++) {
        float s0 = sB[wid][0][j], s1 = sB[wid][1][j];
        float2 wkj = *(const float2*)&wk[j*64 + c];
        float2 wvj = *(const float2*)&wv[j*64 + c];
        float2 waj = *(const float2*)&aw1[(64+j)*64 + c];
        k00 += s0*wkj.x; k01 += s0*wkj.y; k10 += s1*wkj.x; k11 += s1*wkj.y;
        v00 += s0*wvj.x; v01 += s0*wvj.y; v10 += s1*wvj.x; v11 += s1*wvj.y;
        p00 += s0*waj.x; p01 += s0*waj.y; p10 += s1*waj.x; p11 += s1*waj.y;
    }
    *(float2*)&g_k [ r0   *64 + c] = make_float2(k00, k01);
    *(float2*)&g_k [(r0+1)*64 + c] = make_float2(k10, k11);
    *(float2*)&g_v [ r0   *64 + c] = make_float2(v00, v01);
    *(float2*)&g_v [(r0+1)*64 + c] = make_float2(v10, v11);
    *(float2*)&g_rp[ r0   *64 + c] = make_float2(p00, p01);
    *(float2*)&g_rp[(r0+1)*64 + c] = make_float2(p10, p11);
}

// =====================================================================
// Kernel 2: task encoder (6->64 relu ->64 relu) fused with Q projection
// =====================================================================
__global__ void k_task(const float* __restrict__ x,
    const float* __restrict__ w1, const float* __restrict__ b1,
    const float* __restrict__ w2, const float* __restrict__ b2,
    const float* __restrict__ wq, const float* __restrict__ bq)
{
    __shared__ float sA[8][64];
    __shared__ float sB[8][64];
    int wid = threadIdx.x >> 5, lane = threadIdx.x & 31;
    int row = blockIdx.x * 8 + wid;
    const float* xr = x + row * 6;
    float xv[6];
#pragma unroll
    for (int i = 0; i < 6; i++) xv[i] = xr[i];
    int c = lane * 2;

    float ha = b1[c], hb = b1[c+1];
#pragma unroll
    for (int i = 0; i < 6; i++) {
        float2 w = *(const float2*)&w1[i*64 + c];
        ha += xv[i]*w.x; hb += xv[i]*w.y;
    }
    sA[wid][c] = fmaxf(ha, 0.f); sA[wid][c+1] = fmaxf(hb, 0.f);
    __syncwarp();

    float ga = b2[c], gb = b2[c+1];
#pragma unroll 8
    for (int j = 0; j < 64; j++) {
        float2 w = *(const float2*)&w2[j*64 + c];
        float s = sA[wid][j];
        ga += s*w.x; gb += s*w.y;
    }
    sB[wid][c] = fmaxf(ga, 0.f); sB[wid][c+1] = fmaxf(gb, 0.f);
    __syncwarp();

    float qa = bq[c], qb = bq[c+1];
#pragma unroll 8
    for (int j = 0; j < 64; j++) {
        float2 w = *(const float2*)&wq[j*64 + c];
        float s = sB[wid][j];
        qa += s*w.x; qb += s*w.y;
    }
    g_q[row*64 + c] = qa; g_q[row*64 + c+1] = qb;
}

// =====================================================================
// Kernel 3: attention; block per (b,t), 256 threads
// warp-parallel softmax (1 warp per head), parallel epilogue GEMVs
// Produces g_tp = (ctx@wo+bo)@a_w1[:H]+a_b1
// =====================================================================
__global__ void __launch_bounds__(256) k_attn(
    const float* __restrict__ wo, const float* __restrict__ bo,
    const float* __restrict__ aw1, const float* __restrict__ ab1)
{
    int bt = blockIdx.x;
    int b  = bt >> 7;           // T=128
    __shared__ float qs[64];
    __shared__ float lg[4][512];
    __shared__ float invs[4];
    __shared__ float ctxp[4][68];
    __shared__ float ctxs[64];
    __shared__ float tfs[64];
    int t = threadIdx.x, lane = t & 31, wid = t >> 5;

    if (t < 64) qs[t] = g_q[bt*64 + t];
    __syncthreads();

    // logits[h][r] = q_h . k_{r,h} / 4
    const float* kb = g_k + (size_t)b*RR*64;
#pragma unroll
    for (int it = 0; it < 8; it++) {
        int idx = t + it*256;
        int h = idx >> 9, r = idx & 511;
        const float* kr = kb + r*64 + h*16;
        const float* qh = qs + h*16;
        float d = 0.f;
#pragma unroll
        for (int i = 0; i < 16; i += 4) {
            float4 kv = *(const float4*)(kr + i);
            d += qh[i]*kv.x + qh[i+1]*kv.y + qh[i+2]*kv.z + qh[i+3]*kv.w;
        }
        lg[h][r] = d * 0.25f;
    }
    __syncthreads();

    // per-head softmax: warp w handles head w (warps 4-7 idle)
    if (wid < 4) {
        int h = wid;
        float v[16];
        float m = -1e30f;
#pragma unroll
        for (int i = 0; i < 16; i++) { v[i] = lg[h][i*32 + lane]; m = fmaxf(m, v[i]); }
#pragma unroll
        for (int o = 16; o; o >>= 1) m = fmaxf(m, __shfl_xor_sync(0xffffffffu, m, o));
        float s = 0.f;
#pragma unroll
        for (int i = 0; i < 16; i++) {
            float e = __expf(v[i] - m);
            lg[h][i*32 + lane] = e;
            s += e;
        }
#pragma unroll
        for (int o = 16; o; o >>= 1) s += __shfl_xor_sync(0xffffffffu, s, o);
        if (lane == 0) invs[h] = 1.f / s;
    }
    __syncthreads();

    // ctx[col] = sum_r attn[h][r] * v[r][col]  (4 partial groups of 128 r)
    {
        const float* vbp = g_v + (size_t)b*RR*64;
        int part = t >> 6, col = t & 63, h = col >> 4;
        int rbase = part * 128;
        float s = 0.f;
#pragma unroll 4
        for (int r = 0; r < 128; r++)
            s += lg[h][rbase + r] * vbp[(size_t)(rbase + r)*64 + col];
        ctxp[part][col] = s;
    }
    __syncthreads();
    if (t < 64)
        ctxs[t] = (ctxp[0][t] + ctxp[1][t] + ctxp[2][t] + ctxp[3][t]) * invs[t >> 4];
    __syncthreads();

    // tf = ctx@wo + bo  (parallel over 256 threads: 4 j-parts x 64 cols)
    {
        int part = t >> 6, col = t & 63;
        float a = 0.f;
#pragma unroll
        for (int j = part*16; j < part*16 + 16; j++)
            a += ctxs[j]*wo[j*64 + col];
        ctxp[part][col] = a;
    }
    __syncthreads();
    if (t < 64) tfs[t] = ctxp[0][t] + ctxp[1][t] + ctxp[2][t] + ctxp[3][t] + bo[t];
    __syncthreads();

    // tp = tf@a_w1[:H] + a_b1
    {
        int part = t >> 6, col = t & 63;
        float a = 0.f;
#pragma unroll
        for (int j = part*16; j < part*16 + 16; j++)
            a += tfs[j]*aw1[j*64 + col];
        ctxp[part][col] = a;
    }
    __syncthreads();
    if (t < 64)
        g_tp[bt*64 + t] = ctxp[0][t] + ctxp[1][t] + ctxp[2][t] + ctxp[3][t] + ab1[t];
}

// =====================================================================
// Kernel 4 (dominant): pairwise MLP + softmax over robots
// block per (b,t); 128 threads; 4 tiles of 128 robots
// per-thread register tile: 4 robots (strided by 32) x 8 h2-cols
// GEMM accumulators are packed fp32x2 (FFMA2)
// =====================================================================
__global__ void __launch_bounds__(128) k_pair(
    const float* __restrict__ aw2, const float* __restrict__ ab2,
    const float* __restrict__ aw3, float* __restrict__ out)
{
    int bt = blockIdx.x;
    int b  = bt >> 7;
    __shared__ __align__(16) float W2s[64][32];   // a_w2 [64][32]
    __shared__ __align__(16) float b2s[32];
    __shared__ float w3s[32];
    __shared__ __align__(16) float tps[64];
    __shared__ __align__(16) float h1s[128][68];  // robots x H, padded (68*4=272B, 16B-mult)
    __shared__ float sp[4][132];                  // partial scores [colgroup][row]
    __shared__ float sc[512];
    __shared__ float red[8];
    int t = threadIdx.x, lane = t & 31, wid = t >> 5;

    for (int i = t; i < 2048; i += 128) W2s[i >> 5][i & 31] = aw2[i];
    if (t < 32) { b2s[t] = ab2[t]; w3s[t] = aw3[t]; }
    if (t < 64) tps[t] = g_tp[bt*64 + t];
    __syncthreads();

    int tx = t & 3;          // col group: cols tx*8 .. tx*8+7 (pairs tx*4..tx*4+3)
    int ty = t >> 2;         // 0..31 ; rows = ty + 32*m, m=0..3
    const float* rpb = g_rp + (size_t)b*RR*64;

    for (int tile = 0; tile < 4; tile++) {
        int r0 = tile * 128;
        // ---- build h1 tile: relu(tp + rp), 128 rows x 64 cols ----
#pragma unroll
        for (int i = 0; i < 16; i++) {
            int lin = t + i*128;              // 0..2047 float4 slots
            int rr = lin >> 4, j4 = lin & 15;
            float4 rv = *(const float4*)(rpb + (size_t)(r0 + rr)*64 + j4*4);
            float4 tv = *(const float4*)(tps + j4*4);
            float4 hv;
            hv.x = fmaxf(rv.x + tv.x, 0.f);
            hv.y = fmaxf(rv.y + tv.y, 0.f);
            hv.z = fmaxf(rv.z + tv.z, 0.f);
            hv.w = fmaxf(rv.w + tv.w, 0.f);
            *(float4*)(&h1s[rr][j4*4]) = hv;
        }
        __syncthreads();

        // ---- GEMM: [128 x 32] = h1[128 x 64] @ W2[64 x 32], fp32x2 packed ----
        unsigned long long acc[4][4];
#pragma unroll
        for (int m = 0; m < 4; m++)
#pragma unroll
            for (int i = 0; i < 4; i++)
                acc[m][i] = *(const unsigned long long*)&b2s[tx*8 + i*2];

#pragma unroll
        for (int j4 = 0; j4 < 16; j4++) {
            float Aarr[4][4];
#pragma unroll
            for (int m = 0; m < 4; m++)
                *(float4*)Aarr[m] = *(const float4*)(&h1s[ty + 32*m][j4*4]);
#pragma unroll
            for (int kk = 0; kk < 4; kk++) {
                const ulonglong2* wp = (const ulonglong2*)&W2s[j4*4 + kk][tx*8];
                ulonglong2 w01 = wp[0];
                ulonglong2 w23 = wp[1];
#pragma unroll
                for (int m = 0; m < 4; m++) {
                    unsigned long long a2 = pack2(Aarr[m][kk]);
                    fma2(acc[m][0], a2, w01.x);
                    fma2(acc[m][1], a2, w01.y);
                    fma2(acc[m][2], a2, w23.x);
                    fma2(acc[m][3], a2, w23.y);
                }
            }
        }

        // ---- epilogue: relu(h2) . a_w3  (a_b3 cancels in softmax) ----
#pragma unroll
        for (int m = 0; m < 4; m++) {
            float p = 0.f;
#pragma unroll
            for (int i = 0; i < 4; i++) {
                float2 f = unpack2(acc[m][i]);
                p += fmaxf(f.x, 0.f) * w3s[tx*8 + 2*i]
                   + fmaxf(f.y, 0.f) * w3s[tx*8 + 2*i + 1];
            }
            sp[tx][ty + 32*m] = p;
        }
        __syncthreads();
        if (t < 128) sc[r0 + t] = sp[0][t] + sp[1][t] + sp[2][t] + sp[3][t];
        __syncthreads();
    }

    // ---- softmax over 512 robots ----
    float v0 = sc[t], v1 = sc[t+128], v2 = sc[t+256], v3 = sc[t+384];
    float m = fmaxf(fmaxf(v0, v1), fmaxf(v2, v3));
#pragma unroll
    for (int o = 16; o; o >>= 1) m = fmaxf(m, __shfl_xor_sync(0xffffffffu, m, o));
    if (lane == 0) red[wid] = m;
    __syncthreads();
    m = fmaxf(fmaxf(red[0], red[1]), fmaxf(red[2], red[3]));
    v0 = __expf(v0 - m); v1 = __expf(v1 - m); v2 = __expf(v2 - m); v3 = __expf(v3 - m);
    float s = v0 + v1 + v2 + v3;
#pragma unroll
    for (int o = 16; o; o >>= 1) s += __shfl_xor_sync(0xffffffffu, s, o);
    if (lane == 0) red[4 + wid] = s;
    __syncthreads();
    s = red[4] + red[5] + red[6] + red[7];
    float inv = 1.f / s;
    float* op = out + (size_t)bt * 512;
    op[t]     = v0 * inv;
    op[t+128] = v1 * inv;
    op[t+256] = v2 * inv;
    op[t+384] = v3 * inv;
}

// =====================================================================
extern "C" void kernel_launch(void* const* d_in, const int* in_sizes, int n_in,
                              void* d_out, int out_size)
{
    (void)in_sizes; (void)n_in; (void)out_size;
    const float* robot = (const float*)d_in[0];
    const float* task  = (const float*)d_in[1];
    const float* r_w1  = (const float*)d_in[2];
    const float* r_b1  = (const float*)d_in[3];
    const float* r_w2  = (const float*)d_in[4];
    const float* r_b2  = (const float*)d_in[5];
    const float* t_w1  = (const float*)d_in[6];
    const float* t_b1  = (const float*)d_in[7];
    const float* t_w2  = (const float*)d_in[8];
    const float* t_b2  = (const float*)d_in[9];
    const float* wq    = (const float*)d_in[10];
    const float* bq    = (const float*)d_in[11];
    const float* wk    = (const float*)d_in[12];
    const float* bk    = (const float*)d_in[13];
    const float* wv    = (const float*)d_in[14];
    const float* bv    = (const float*)d_in[15];
    const float* wo    = (const float*)d_in[16];
    const float* bo    = (const float*)d_in[17];
    const float* a_w1  = (const float*)d_in[18];
    const float* a_b1  = (const float*)d_in[19];
    const float* a_w2  = (const float*)d_in[20];
    const float* a_b2  = (const float*)d_in[21];
    const float* a_w3  = (const float*)d_in[22];

    k_robot<<<BB*RR/16, 256>>>(robot, r_w1, r_b1, r_w2, r_b2, wk, bk, wv, bv, a_w1);
    k_task <<<BB*TT/8,  256>>>(task, t_w1, t_b1, t_w2, t_b2, wq, bq);
    k_attn <<<BB*TT,    256>>>(wo, bo, a_w1, a_b1);
    k_pair <<<BB*TT,    128>>>(a_w2, a_b2, a_w3, (float*)d_out);
}

// round 6
// speedup vs baseline: 1.7790x; 1.3169x over previous
#include <cuda_runtime.h>

#define BB 32
#define RR 512
#define TT 128
#define HH 64

// ---- scratch (device globals; no allocations) ----
__device__ float g_k [BB*RR*HH];
__device__ float g_v [BB*RR*HH];
__device__ float g_rp[BB*RR*HH];
__device__ float g_q [BB*TT*HH];
__device__ float g_tp[BB*TT*HH];

// ---- packed fp32x2 helpers (Blackwell FFMA2 path) ----
__device__ __forceinline__ unsigned long long pack2(float a) {
    unsigned long long r;
    asm("mov.b64 %0, {%1, %1};" : "=l"(r) : "f"(a));
    return r;
}
__device__ __forceinline__ void fma2(unsigned long long& d, unsigned long long a, unsigned long long b) {
    asm("fma.rn.f32x2 %0, %1, %2, %3;" : "=l"(d) : "l"(a), "l"(b), "l"(d));
}
__device__ __forceinline__ float2 unpack2(unsigned long long v) {
    float2 f;
    asm("mov.b64 {%0, %1}, %2;" : "=f"(f.x), "=f"(f.y) : "l"(v));
    return f;
}

// =====================================================================
// Kernel 1: robot encoder fused with K,V,rp projections. 4 rows/warp.
// =====================================================================
__global__ void __launch_bounds__(256) k_robot(const float* __restrict__ x,
    const float* __restrict__ w1, const float* __restrict__ b1,
    const float* __restrict__ w2, const float* __restrict__ b2,
    const float* __restrict__ wk, const float* __restrict__ bk,
    const float* __restrict__ wv, const float* __restrict__ bv,
    const float* __restrict__ aw1)
{
    __shared__ float sA[8][4][64];
    __shared__ float sB[8][4][64];
    int wid = threadIdx.x >> 5, lane = threadIdx.x & 31;
    int r0 = blockIdx.x * 32 + wid * 4;
    int c = lane * 2;
    const float* xp = x + r0 * 7;

    float xv[4][7];
#pragma unroll
    for (int rr = 0; rr < 4; rr++)
#pragma unroll
        for (int i = 0; i < 7; i++) xv[rr][i] = xp[rr*7 + i];

    // layer 1
    float2 b1v = *(const float2*)&b1[c];
    float h[4][2];
#pragma unroll
    for (int rr = 0; rr < 4; rr++) { h[rr][0] = b1v.x; h[rr][1] = b1v.y; }
#pragma unroll
    for (int i = 0; i < 7; i++) {
        float2 w = *(const float2*)&w1[i*64 + c];
#pragma unroll
        for (int rr = 0; rr < 4; rr++) { h[rr][0] += xv[rr][i]*w.x; h[rr][1] += xv[rr][i]*w.y; }
    }
#pragma unroll
    for (int rr = 0; rr < 4; rr++) {
        sA[wid][rr][c]   = fmaxf(h[rr][0], 0.f);
        sA[wid][rr][c+1] = fmaxf(h[rr][1], 0.f);
    }
    __syncwarp();

    // layer 2
    float2 b2v = *(const float2*)&b2[c];
    float g[4][2];
#pragma unroll
    for (int rr = 0; rr < 4; rr++) { g[rr][0] = b2v.x; g[rr][1] = b2v.y; }
#pragma unroll 4
    for (int j = 0; j < 64; j++) {
        float2 w = *(const float2*)&w2[j*64 + c];
#pragma unroll
        for (int rr = 0; rr < 4; rr++) {
            float s = sA[wid][rr][j];
            g[rr][0] += s*w.x; g[rr][1] += s*w.y;
        }
    }
#pragma unroll
    for (int rr = 0; rr < 4; rr++) {
        sB[wid][rr][c]   = fmaxf(g[rr][0], 0.f);
        sB[wid][rr][c+1] = fmaxf(g[rr][1], 0.f);
    }
    __syncwarp();

    // fused K, V, rp projections
    float2 bkv = *(const float2*)&bk[c];
    float2 bvv = *(const float2*)&bv[c];
    float ka[4][2], va[4][2], pa[4][2];
#pragma unroll
    for (int rr = 0; rr < 4; rr++) {
        ka[rr][0] = bkv.x; ka[rr][1] = bkv.y;
        va[rr][0] = bvv.x; va[rr][1] = bvv.y;
        pa[rr][0] = 0.f;   pa[rr][1] = 0.f;
    }
#pragma unroll 2
    for (int j = 0; j < 64; j++) {
        float2 wkj = *(const float2*)&wk[j*64 + c];
        float2 wvj = *(const float2*)&wv[j*64 + c];
        float2 waj = *(const float2*)&aw1[(64+j)*64 + c];
#pragma unroll
        for (int rr = 0; rr < 4; rr++) {
            float s = sB[wid][rr][j];
            ka[rr][0] += s*wkj.x; ka[rr][1] += s*wkj.y;
            va[rr][0] += s*wvj.x; va[rr][1] += s*wvj.y;
            pa[rr][0] += s*waj.x; pa[rr][1] += s*waj.y;
        }
    }
#pragma unroll
    for (int rr = 0; rr < 4; rr++) {
        *(float2*)&g_k [(r0+rr)*64 + c] = make_float2(ka[rr][0], ka[rr][1]);
        *(float2*)&g_v [(r0+rr)*64 + c] = make_float2(va[rr][0], va[rr][1]);
        *(float2*)&g_rp[(r0+rr)*64 + c] = make_float2(pa[rr][0], pa[rr][1]);
    }
}

// =====================================================================
// Kernel 2: task encoder fused with Q projection (unchanged)
// =====================================================================
__global__ void k_task(const float* __restrict__ x,
    const float* __restrict__ w1, const float* __restrict__ b1,
    const float* __restrict__ w2, const float* __restrict__ b2,
    const float* __restrict__ wq, const float* __restrict__ bq)
{
    __shared__ float sA[8][64];
    __shared__ float sB[8][64];
    int wid = threadIdx.x >> 5, lane = threadIdx.x & 31;
    int row = blockIdx.x * 8 + wid;
    const float* xr = x + row * 6;
    float xv[6];
#pragma unroll
    for (int i = 0; i < 6; i++) xv[i] = xr[i];
    int c = lane * 2;

    float ha = b1[c], hb = b1[c+1];
#pragma unroll
    for (int i = 0; i < 6; i++) {
        float2 w = *(const float2*)&w1[i*64 + c];
        ha += xv[i]*w.x; hb += xv[i]*w.y;
    }
    sA[wid][c] = fmaxf(ha, 0.f); sA[wid][c+1] = fmaxf(hb, 0.f);
    __syncwarp();

    float ga = b2[c], gb = b2[c+1];
#pragma unroll 8
    for (int j = 0; j < 64; j++) {
        float2 w = *(const float2*)&w2[j*64 + c];
        float s = sA[wid][j];
        ga += s*w.x; gb += s*w.y;
    }
    sB[wid][c] = fmaxf(ga, 0.f); sB[wid][c+1] = fmaxf(gb, 0.f);
    __syncwarp();

    float qa = bq[c], qb = bq[c+1];
#pragma unroll 8
    for (int j = 0; j < 64; j++) {
        float2 w = *(const float2*)&wq[j*64 + c];
        float s = sB[wid][j];
        qa += s*w.x; qb += s*w.y;
    }
    g_q[row*64 + c] = qa; g_q[row*64 + c+1] = qb;
}

// =====================================================================
// Kernel 3: attention, 8 tasks per block (grid = B*16 = 512), 256 thr
// K/V streamed in 128-robot SMEM chunks, reused by 8 tasks.
// dynamic smem layout (floats):
//   AQ   : q            8*64         =   512
//   ALG  : logits/attn  8*4*512      = 16384
//   AKV  : K/V chunk    128*68       =  8704  (reused for wo/aw1)
//   AINV : 1/sum        32
//   ACS  : ctx          8*64         =   512
//   ATF  : tf           8*64         =   512
// =====================================================================
#define AQ   0
#define ALG  512
#define AKV  16896
#define AINV 25600
#define ACS  25632
#define ATF  26144
#define ATTN_SMEM_FLOATS 26656

__global__ void __launch_bounds__(256) k_attn(
    const float* __restrict__ wo, const float* __restrict__ bo,
    const float* __restrict__ aw1, const float* __restrict__ ab1)
{
    extern __shared__ float sm[];
    int blk = blockIdx.x;
    int b = blk >> 4;
    int tk0 = (blk & 15) * 8;
    int t = threadIdx.x, lane = t & 31, w = t >> 5;

    // load q for 8 tasks
    for (int i = t; i < 512; i += 256)
        sm[AQ + i] = g_q[(size_t)(b*128 + tk0 + (i >> 6))*64 + (i & 63)];

    const float* kb = g_k + (size_t)b*RR*64;
    const float* vb = g_v + (size_t)b*RR*64;

    // ---- logits ----
    for (int chunk = 0; chunk < 4; chunk++) {
        __syncthreads();
        // load K chunk [128][64] -> [128][68]
#pragma unroll
        for (int i = 0; i < 8; i++) {
            int lin = t + i*256;
            int row = lin >> 4, c4 = lin & 15;
            float4 kvv = *(const float4*)(kb + (size_t)(chunk*128 + row)*64 + c4*4);
            *(float4*)&sm[AKV + row*68 + c4*4] = kvv;
        }
        __syncthreads();
        // 4096 dots / 256 threads = 16 each
#pragma unroll
        for (int i = 0; i < 16; i++) {
            int idx = i*256 + t;
            int th = idx >> 7, r = idx & 127;
            int task = th >> 2, h = th & 3;
            const float* kr = &sm[AKV + r*68 + h*16];
            const float* qh = &sm[AQ + task*64 + h*16];
            float d = 0.f;
#pragma unroll
            for (int j = 0; j < 16; j += 4) {
                float4 kv4 = *(const float4*)(kr + j);
                float4 q4  = *(const float4*)(qh + j);
                d += kv4.x*q4.x + kv4.y*q4.y + kv4.z*q4.z + kv4.w*q4.w;
            }
            sm[ALG + (task*4 + h)*512 + chunk*128 + r] = d * 0.25f;
        }
    }
    __syncthreads();

    // ---- softmax per (task,head): 32 rows of 512, warp per row ----
    for (int p = w; p < 32; p += 8) {
        float* base = &sm[ALG + p*512];
        float v[16];
        float m = -1e30f;
#pragma unroll
        for (int i = 0; i < 16; i++) { v[i] = base[i*32 + lane]; m = fmaxf(m, v[i]); }
#pragma unroll
        for (int o = 16; o; o >>= 1) m = fmaxf(m, __shfl_xor_sync(0xffffffffu, m, o));
        float s = 0.f;
#pragma unroll
        for (int i = 0; i < 16; i++) {
            float e = __expf(v[i] - m);
            base[i*32 + lane] = e;
            s += e;
        }
#pragma unroll
        for (int o = 16; o; o >>= 1) s += __shfl_xor_sync(0xffffffffu, s, o);
        if (lane == 0) sm[AINV + p] = 1.f / s;
    }
    __syncthreads();

    // ---- AV: thread -> (task = t>>5, col pair c2, c2+1) ----
    int task = t >> 5;
    int c2 = (t & 31) * 2;
    int hh = c2 >> 4;
    float acc0 = 0.f, acc1 = 0.f;
    for (int chunk = 0; chunk < 4; chunk++) {
        __syncthreads();
#pragma unroll
        for (int i = 0; i < 8; i++) {
            int lin = t + i*256;
            int row = lin >> 4, c4 = lin & 15;
            float4 vvv = *(const float4*)(vb + (size_t)(chunk*128 + row)*64 + c4*4);
            *(float4*)&sm[AKV + row*68 + c4*4] = vvv;
        }
        __syncthreads();
        const float* lgp = &sm[ALG + (task*4 + hh)*512 + chunk*128];
#pragma unroll 4
        for (int r = 0; r < 128; r++) {
            float a = lgp[r];
            float2 vv = *(const float2*)&sm[AKV + r*68 + c2];
            acc0 += a*vv.x; acc1 += a*vv.y;
        }
    }
    __syncthreads();   // AV done; AKV free for weights

    // scaled ctx
    {
        float inv = sm[AINV + task*4 + hh];
        sm[ACS + task*64 + c2]     = acc0 * inv;
        sm[ACS + task*64 + c2 + 1] = acc1 * inv;
    }
    // stage wo and aw1[:64] in AKV
#pragma unroll
    for (int i = 0; i < 4; i++) {
        int lin = t + i*256;  // 0..1023 float4 slots
        *(float4*)&sm[AKV + lin*4]        = *(const float4*)(wo  + lin*4);
        *(float4*)&sm[AKV + 4096 + lin*4] = *(const float4*)(aw1 + lin*4);
    }
    __syncthreads();

    // per-warp task epilogue: tf = ctx@wo + bo ; tp = tf@aw1 + ab1
    {
        int c = lane * 2;
        float2 bov = *(const float2*)&bo[c];
        float f0 = bov.x, f1 = bov.y;
#pragma unroll 8
        for (int j = 0; j < 64; j++) {
            float s = sm[ACS + w*64 + j];
            float2 ww = *(const float2*)&sm[AKV + j*64 + c];
            f0 += s*ww.x; f1 += s*ww.y;
        }
        sm[ATF + w*64 + c] = f0; sm[ATF + w*64 + c + 1] = f1;
        __syncwarp();
        float2 abv = *(const float2*)&ab1[c];
        float p0 = abv.x, p1 = abv.y;
#pragma unroll 8
        for (int j = 0; j < 64; j++) {
            float s = sm[ATF + w*64 + j];
            float2 ww = *(const float2*)&sm[AKV + 4096 + j*64 + c];
            p0 += s*ww.x; p1 += s*ww.y;
        }
        *(float2*)&g_tp[(size_t)(b*128 + tk0 + w)*64 + c] = make_float2(p0, p1);
    }
}

// =====================================================================
// Kernel 4 (dominant): pairwise MLP + softmax. block per (b,t), 128 thr
// 2 tiles of 256 robots; thread tile 8 rows (ty+32m) x 8 cols; FFMA2.
// dynamic smem (floats):
//   PW2 0 (2048) | PB2 2048 (32) | PW3 2080 (32) | PTPS 2112 (64)
//   PH1 2176 (256*68=17408) | PSP 19584 (4*260=1040) | PSC 20624 (512)
//   PRED 21136 (8)
// =====================================================================
#define PW2  0
#define PB2  2048
#define PW3  2080
#define PTPS 2112
#define PH1  2176
#define PSP  19584
#define PSC  20624
#define PRED 21136
#define PAIR_SMEM_FLOATS 21152

__global__ void __launch_bounds__(128) k_pair(
    const float* __restrict__ aw2, const float* __restrict__ ab2,
    const float* __restrict__ aw3, float* __restrict__ out)
{
    extern __shared__ float sm[];
    int bt = blockIdx.x;
    int b  = bt >> 7;
    int t = threadIdx.x, lane = t & 31, wid = t >> 5;

    for (int i = t; i < 2048; i += 128) sm[PW2 + i] = aw2[i];
    if (t < 32) { sm[PB2 + t] = ab2[t]; sm[PW3 + t] = aw3[t]; }
    if (t < 64) sm[PTPS + t] = g_tp[bt*64 + t];
    __syncthreads();

    int tx = t & 3;       // col group: cols tx*8 .. +7
    int ty = t >> 2;      // 0..31 ; rows = ty + 32m, m = 0..7
    const float* rpb = g_rp + (size_t)b*RR*64;

    int bj4 = t & 15;           // fixed column-quad for h1 build
    int brb = t >> 4;           // 0..7 base row
    float4 tv = *(const float4*)&sm[PTPS + bj4*4];

    for (int tile = 0; tile < 2; tile++) {
        int r0 = tile * 256;
        // ---- build h1 tile: relu(tp + rp), 256 rows x 64 cols ----
#pragma unroll
        for (int i = 0; i < 32; i++) {
            int rr = brb + i*8;
            float4 rv = *(const float4*)(rpb + (size_t)(r0 + rr)*64 + bj4*4);
            float4 hv;
            hv.x = fmaxf(rv.x + tv.x, 0.f);
            hv.y = fmaxf(rv.y + tv.y, 0.f);
            hv.z = fmaxf(rv.z + tv.z, 0.f);
            hv.w = fmaxf(rv.w + tv.w, 0.f);
            *(float4*)&sm[PH1 + rr*68 + bj4*4] = hv;
        }
        __syncthreads();

        // ---- GEMM: [256 x 32] = h1[256 x 64] @ W2[64 x 32] ----
        unsigned long long acc[8][4];
#pragma unroll
        for (int m = 0; m < 8; m++)
#pragma unroll
            for (int i = 0; i < 4; i++)
                acc[m][i] = *(const unsigned long long*)&sm[PB2 + tx*8 + i*2];

#pragma unroll
        for (int j4 = 0; j4 < 16; j4++) {
            float Aa[8][4];
#pragma unroll
            for (int m = 0; m < 8; m++)
                *(float4*)Aa[m] = *(const float4*)&sm[PH1 + (ty + 32*m)*68 + j4*4];
#pragma unroll
            for (int kk = 0; kk < 4; kk++) {
                const ulonglong2* wp = (const ulonglong2*)&sm[PW2 + (j4*4 + kk)*32 + tx*8];
                ulonglong2 w01 = wp[0];
                ulonglong2 w23 = wp[1];
#pragma unroll
                for (int m = 0; m < 8; m++) {
                    unsigned long long a2 = pack2(Aa[m][kk]);
                    fma2(acc[m][0], a2, w01.x);
                    fma2(acc[m][1], a2, w01.y);
                    fma2(acc[m][2], a2, w23.x);
                    fma2(acc[m][3], a2, w23.y);
                }
            }
        }

        // ---- epilogue: relu(h2) . a_w3 ----
#pragma unroll
        for (int m = 0; m < 8; m++) {
            float p = 0.f;
#pragma unroll
            for (int i = 0; i < 4; i++) {
                float2 f = unpack2(acc[m][i]);
                p += fmaxf(f.x, 0.f) * sm[PW3 + tx*8 + 2*i]
                   + fmaxf(f.y, 0.f) * sm[PW3 + tx*8 + 2*i + 1];
            }
            sm[PSP + tx*260 + ty + 32*m] = p;
        }
        __syncthreads();
        sm[PSC + r0 + t]       = sm[PSP + t]       + sm[PSP + 260 + t]       + sm[PSP + 520 + t]       + sm[PSP + 780 + t];
        sm[PSC + r0 + t + 128] = sm[PSP + t + 128] + sm[PSP + 260 + t + 128] + sm[PSP + 520 + t + 128] + sm[PSP + 780 + t + 128];
        __syncthreads();
    }

    // ---- softmax over 512 robots ----
    float v0 = sm[PSC + t], v1 = sm[PSC + t + 128], v2 = sm[PSC + t + 256], v3 = sm[PSC + t + 384];
    float m = fmaxf(fmaxf(v0, v1), fmaxf(v2, v3));
#pragma unroll
    for (int o = 16; o; o >>= 1) m = fmaxf(m, __shfl_xor_sync(0xffffffffu, m, o));
    if (lane == 0) sm[PRED + wid] = m;
    __syncthreads();
    m = fmaxf(fmaxf(sm[PRED + 0], sm[PRED + 1]), fmaxf(sm[PRED + 2], sm[PRED + 3]));
    v0 = __expf(v0 - m); v1 = __expf(v1 - m); v2 = __expf(v2 - m); v3 = __expf(v3 - m);
    float s = v0 + v1 + v2 + v3;
#pragma unroll
    for (int o = 16; o; o >>= 1) s += __shfl_xor_sync(0xffffffffu, s, o);
    if (lane == 0) sm[PRED + 4 + wid] = s;
    __syncthreads();
    s = sm[PRED + 4] + sm[PRED + 5] + sm[PRED + 6] + sm[PRED + 7];
    float inv = 1.f / s;
    float* op = out + (size_t)bt * 512;
    op[t]     = v0 * inv;
    op[t+128] = v1 * inv;
    op[t+256] = v2 * inv;
    op[t+384] = v3 * inv;
}

// =====================================================================
extern "C" void kernel_launch(void* const* d_in, const int* in_sizes, int n_in,
                              void* d_out, int out_size)
{
    (void)in_sizes; (void)n_in; (void)out_size;
    const float* robot = (const float*)d_in[0];
    const float* task  = (const float*)d_in[1];
    const float* r_w1  = (const float*)d_in[2];
    const float* r_b1  = (const float*)d_in[3];
    const float* r_w2  = (const float*)d_in[4];
    const float* r_b2  = (const float*)d_in[5];
    const float* t_w1  = (const float*)d_in[6];
    const float* t_b1  = (const float*)d_in[7];
    const float* t_w2  = (const float*)d_in[8];
    const float* t_b2  = (const float*)d_in[9];
    const float* wq    = (const float*)d_in[10];
    const float* bq    = (const float*)d_in[11];
    const float* wk    = (const float*)d_in[12];
    const float* bk    = (const float*)d_in[13];
    const float* wv    = (const float*)d_in[14];
    const float* bv    = (const float*)d_in[15];
    const float* wo    = (const float*)d_in[16];
    const float* bo    = (const float*)d_in[17];
    const float* a_w1  = (const float*)d_in[18];
    const float* a_b1  = (const float*)d_in[19];
    const float* a_w2  = (const float*)d_in[20];
    const float* a_b2  = (const float*)d_in[21];
    const float* a_w3  = (const float*)d_in[22];

    static_assert(ATTN_SMEM_FLOATS * 4 < 230000, "attn smem");
    static_assert(PAIR_SMEM_FLOATS * 4 < 230000, "pair smem");
    cudaFuncSetAttribute(k_attn, cudaFuncAttributeMaxDynamicSharedMemorySize, ATTN_SMEM_FLOATS * 4);
    cudaFuncSetAttribute(k_pair, cudaFuncAttributeMaxDynamicSharedMemorySize, PAIR_SMEM_FLOATS * 4);

    k_robot<<<BB*RR/32, 256>>>(robot, r_w1, r_b1, r_w2, r_b2, wk, bk, wv, bv, a_w1);
    k_task <<<BB*TT/8,  256>>>(task, t_w1, t_b1, t_w2, t_b2, wq, bq);
    k_attn <<<BB*16,    256, ATTN_SMEM_FLOATS * 4>>>(wo, bo, a_w1, a_b1);
    k_pair <<<BB*TT,    128, PAIR_SMEM_FLOATS * 4>>>(a_w2, a_b2, a_w3, (float*)d_out);
}